// round 14
// baseline (speedup 1.0000x reference)
#include <cuda_runtime.h>
#include <cstdint>

// HOG fused kernel R14: fill keeps own pixel rows in registers (no redundant
// LDG), tile serves only vertical-halo rows + horizontal-halo scalars.
// 9-slot mod-9 histogram, paired overlapped RMW, register fold epilogue.
// x: (64,1,512,512) f32. out: (64, 9*64*64) f32.
// Block = (image n, cell-row cy) stripe, 256 threads: cell = t/4, sub = t%4 (2 rows).
// Tile rows 0..9 = stripe rows -1..8; col c -> 10*(c>>3)+(c&7)+4.
// Cell c window: left halo idx 10c+1 (= cell c-1 col 7), data 10c+4..11,
// right halo 10c+14 (= cell c+1 col 0); image-edge pads idx 1 / 644.

#define TS2 646

__device__ __forceinline__ uint32_t smem_u32(const void* p)
{
    uint32_t a;
    asm("{ .reg .u64 t; cvta.to.shared.u64 t, %1; cvt.u32.u64 %0, t; }"
        : "=r"(a) : "l"(p));
    return a;
}

__device__ __forceinline__ float setge(float a, float b)
{
    float r;
    asm("set.ge.f32.f32 %0, %1, %2;" : "=f"(r) : "f"(a), "f"(b));
    return r;
}

// 9-slot histogram bucket address; slot = |fa - (signs_differ ? 8 : 0)| = fl mod 9
__device__ __forceinline__ uint32_t hog_class(float gx, float gy, uint32_t hb, float& mag)
{
    float d2 = fmaf(gx, gx, gy * gy);
    asm("sqrt.approx.f32 %0, %1;" : "=f"(mag) : "f"(d2));

    float u = fabsf(gx), v = fabsf(gy);
    float fa = (setge(u, 0.36397023f * v) + setge(u, 0.83909963f * v))
             + (setge(u, 1.73205081f * v) + setge(u, 5.67128182f * v));  // 0..4

    uint32_t xo = __float_as_uint(gx) ^ __float_as_uint(gy);
    float cf8 = ((int)xo < 0) ? 8.0f : 0.0f;
    float m = fabsf(fa - cf8) + 12582912.0f;     // 0x4B400000 + slot (exact)
    return hb + (__float_as_uint(m) << 10);
}

__device__ __forceinline__ void hog_pair(uint32_t a0, float m0, uint32_t a1, float m1)
{
    float msum = m0 + m1;
    asm volatile(
        "{\n\t"
        ".reg .pred p;\n\t"
        ".reg .f32 t0, t1, v0;\n\t"
        "setp.ne.u32 p, %0, %1;\n\t"
        "selp.f32 v0, %2, %3, p;\n\t"
        "ld.shared.f32 t0, [%0];\n\t"
        "@p ld.shared.f32 t1, [%1];\n\t"
        "add.f32 t0, t0, v0;\n\t"
        "@p add.f32 t1, t1, %4;\n\t"
        "st.shared.f32 [%0], t0;\n\t"
        "@p st.shared.f32 [%1], t1;\n\t"
        "}"
        :: "r"(a0), "r"(a1), "f"(m0), "f"(msum), "f"(m1));
}

__device__ __forceinline__ void emit(uint32_t hb, float gx0, float gy0, float gx1, float gy1)
{
    float m0, m1;
    uint32_t q0 = hog_class(gx0, gy0, hb, m0);
    uint32_t q1 = hog_class(gx1, gy1, hb, m1);
    hog_pair(q0, m0, q1, m1);
}

__global__ __launch_bounds__(256, 5)
void hog_kernel(const float* __restrict__ x, float* __restrict__ out)
{
    __shared__ __align__(16) float tile[10 * TS2];
    __shared__ float hist[9 * 256];

    const int tid  = threadIdx.x;
    const int n    = blockIdx.x >> 6;
    const int cy   = blockIdx.x & 63;
    const int cell = tid >> 2;
    const int sub  = tid & 3;
    const uint32_t hb = smem_u32(&hist[tid]);

#pragma unroll
    for (int b = 0; b < 9; ++b) hist[b * 256 + tid] = 0.0f;

    const float* img  = x + (size_t)n * (512 * 512);
    const int    row0 = cy * 8;
    const int    c0   = cell * 8;

    // ---- own pixel rows (2s, 2s+1) -> registers, once; always in-range ----
    const float* pmg = img + (size_t)(row0 + 2 * sub) * 512 + c0;
    const float* png = pmg + 512;
    float4 Lm = *reinterpret_cast<const float4*>(pmg);
    float4 Rm = *reinterpret_cast<const float4*>(pmg + 4);
    float4 Ln = *reinterpret_cast<const float4*>(png);
    float4 Rn = *reinterpret_cast<const float4*>(png + 4);

    // ---- halo-row chunk: 256 threads cover rows {-1, 8} x 128 chunks ----
    const int hk = tid & 127;
    const int hr = (tid < 128) ? (row0 - 1) : (row0 + 8);
    float4 hv = make_float4(0.f, 0.f, 0.f, 0.f);
    if ((unsigned)hr < 512u)
        hv = *reinterpret_cast<const float4*>(img + (size_t)hr * 512 + hk * 4);

    // ---- store everything to tile (stride-10 layout) ----
    {
        float* tm = &tile[(2 * sub + 1) * TS2 + 10 * cell + 4];   // stripe row 2s
        float* tn = &tile[(2 * sub + 2) * TS2 + 10 * cell + 4];   // stripe row 2s+1
        *reinterpret_cast<float2*>(tm)     = make_float2(Lm.x, Lm.y);
        *reinterpret_cast<float2*>(tm + 2) = make_float2(Lm.z, Lm.w);
        *reinterpret_cast<float2*>(tm + 4) = make_float2(Rm.x, Rm.y);
        *reinterpret_cast<float2*>(tm + 6) = make_float2(Rm.z, Rm.w);
        *reinterpret_cast<float2*>(tn)     = make_float2(Ln.x, Ln.y);
        *reinterpret_cast<float2*>(tn + 2) = make_float2(Ln.z, Ln.w);
        *reinterpret_cast<float2*>(tn + 4) = make_float2(Rn.x, Rn.y);
        *reinterpret_cast<float2*>(tn + 6) = make_float2(Rn.z, Rn.w);
        float* th = &tile[((tid < 128) ? 0 : 9) * TS2 + 5 * hk + 4 - (hk & 1)];
        *reinterpret_cast<float2*>(th)     = make_float2(hv.x, hv.y);
        *reinterpret_cast<float2*>(th + 2) = make_float2(hv.z, hv.w);
    }
    if (tid < 10) { tile[tid * TS2 + 1] = 0.f; tile[tid * TS2 + 644] = 0.f; }  // edge pads
    __syncthreads();

    // ---- own rows as arrays; horizontal halos from tile (neighbor data) ----
    float m[10], nn[10];
    m[1] = Lm.x; m[2] = Lm.y; m[3] = Lm.z; m[4] = Lm.w;
    m[5] = Rm.x; m[6] = Rm.y; m[7] = Rm.z; m[8] = Rm.w;
    nn[1] = Ln.x; nn[2] = Ln.y; nn[3] = Ln.z; nn[4] = Ln.w;
    nn[5] = Rn.x; nn[6] = Rn.y; nn[7] = Rn.z; nn[8] = Rn.w;
    m[0]  = tile[(2 * sub + 1) * TS2 + 10 * cell + 1];
    m[9]  = tile[(2 * sub + 1) * TS2 + 10 * cell + 14];
    nn[0] = tile[(2 * sub + 2) * TS2 + 10 * cell + 1];
    nn[9] = tile[(2 * sub + 2) * TS2 + 10 * cell + 14];

    // vertical-halo rows: top = stripe 2s-1 (tile row 2s), bottom = stripe 2s+2 (tile 2s+3)
    const float* pt = &tile[(2 * sub + 0) * TS2 + 10 * cell];
    const float* pq = &tile[(2 * sub + 3) * TS2 + 10 * cell];

    // ---- mainloop (R10-validated): streamed halo rows, 2 cols per step ----
    float lw = pt[1], lc = pq[1];
    float2 wp = *reinterpret_cast<const float2*>(pt + 4);
    float2 cp = *reinterpret_cast<const float2*>(pq + 4);

    float Am1 = lw + 2.f * m[0] + nn[0];
    float Bm1 = m[0] + 2.f * nn[0] + lc;
    float A0 = wp.x + 2.f * m[1] + nn[1], A1 = wp.y + 2.f * m[2] + nn[2];
    float B0 = m[1] + 2.f * nn[1] + cp.x, B1 = m[2] + 2.f * nn[2] + cp.y;

    // col 0
    emit(hb,
         Am1 - A1, (lw + 2.f * wp.x + wp.y) - (nn[0] + 2.f * nn[1] + nn[2]),
         Bm1 - B1, (m[0] + 2.f * m[1] + m[2]) - (lc + 2.f * cp.x + cp.y));

    float w0 = wp.x, w1 = wp.y, c0v = cp.x, c1v = cp.y;

#pragma unroll
    for (int k = 1; k < 4; ++k) {
        float2 wn2 = *reinterpret_cast<const float2*>(pt + 4 + 2 * k);
        float2 cn2 = *reinterpret_cast<const float2*>(pq + 4 + 2 * k);
        int j = 2 * k + 1;   // m/nn indices j, j+1
        float A2 = wn2.x + 2.f * m[j] + nn[j],     A3 = wn2.y + 2.f * m[j + 1] + nn[j + 1];
        float B2 = m[j] + 2.f * nn[j] + cn2.x,     B3 = m[j + 1] + 2.f * nn[j + 1] + cn2.y;

        // col 2k-1
        emit(hb,
             A0 - A2, (w0 + 2.f * w1 + wn2.x) - (nn[j - 2] + 2.f * nn[j - 1] + nn[j]),
             B0 - B2, (m[j - 2] + 2.f * m[j - 1] + m[j]) - (c0v + 2.f * c1v + cn2.x));
        // col 2k
        emit(hb,
             A1 - A3, (w1 + 2.f * wn2.x + wn2.y) - (nn[j - 1] + 2.f * nn[j] + nn[j + 1]),
             B1 - B3, (m[j - 1] + 2.f * m[j] + m[j + 1]) - (c1v + 2.f * cn2.x + cn2.y));

        w0 = wn2.x; w1 = wn2.y; c0v = cn2.x; c1v = cn2.y;
        A0 = A2; A1 = A3; B0 = B2; B1 = B3;
    }

    // col 7 with right halo (col 8)
    {
        float rw = pt[14], rc = pq[14];
        float A8 = rw + 2.f * m[9] + nn[9];
        float B8 = m[9] + 2.f * nn[9] + rc;
        emit(hb,
             A0 - A8, (w0 + 2.f * w1 + rw) - (nn[7] + 2.f * nn[8] + nn[9]),
             B0 - B8, (m[7] + 2.f * m[8] + m[9]) - (c0v + 2.f * c1v + rc));
    }

    asm volatile("" ::: "memory");   // order fold reads after asm RMWs

    // ---- fold: bin[b] = P9[b] + P9[(b+8)%9]; shuffle-reduce 4 subs; write ----
    float P[9];
#pragma unroll
    for (int s = 0; s < 9; ++s) P[s] = hist[s * 256 + tid];
    float bin[9];
#pragma unroll
    for (int b = 0; b < 9; ++b) bin[b] = P[b] + P[(b + 8) % 9];

#pragma unroll
    for (int b = 0; b < 9; ++b) {
        bin[b] += __shfl_xor_sync(0xffffffffu, bin[b], 1);
        bin[b] += __shfl_xor_sync(0xffffffffu, bin[b], 2);
    }

    if (sub == 0) {
        float* o = out + (size_t)n * 36864 + cy * 64 + cell;
#pragma unroll
        for (int b = 0; b < 9; ++b)
            o[(size_t)b * 4096] = bin[b] * 0.015625f;   // 1/64
    }
}

extern "C" void kernel_launch(void* const* d_in, const int* in_sizes, int n_in,
                              void* d_out, int out_size)
{
    const float* x = (const float*)d_in[0];
    float* out = (float*)d_out;
    (void)in_sizes; (void)n_in; (void)out_size;
    hog_kernel<<<4096, 256>>>(x, out);
}

// round 15
// speedup vs baseline: 1.0761x; 1.0761x over previous
#include <cuda_runtime.h>
#include <cstdint>

// HOG fused kernel R15: stride-10 tile filled via 8-byte cp.async (no register
// staging, no STS), 6 blocks/SM, 9-slot mod-9 histogram, paired overlapped RMW.
// x: (64,1,512,512) f32. out: (64, 9*64*64) f32.
// Block = (image n, cell-row cy) stripe, 256 threads: cell = t/4, sub = t%4 (2 rows).
// Tile: col c -> 10*(c>>3) + (c&7) + 4 (cell stride 10, conflict-free);
// halos shared with neighbors (10c+1 / 10c+14); image-edge pads idx 1 / 644.

#define TS2 646

__device__ __forceinline__ uint32_t smem_u32(const void* p)
{
    uint32_t a;
    asm("{ .reg .u64 t; cvta.to.shared.u64 t, %1; cvt.u32.u64 %0, t; }"
        : "=r"(a) : "l"(p));
    return a;
}

__device__ __forceinline__ void cp_async8(uint32_t dst, const float* src)
{
    asm volatile("cp.async.ca.shared.global [%0], [%1], 8;"
                 :: "r"(dst), "l"(src));
}

__device__ __forceinline__ void cp_async8_zero(uint32_t dst, const float* src)
{
    asm volatile("cp.async.ca.shared.global [%0], [%1], 8, 0;"   // zero-fill
                 :: "r"(dst), "l"(src));
}

__device__ __forceinline__ float setge(float a, float b)
{
    float r;
    asm("set.ge.f32.f32 %0, %1, %2;" : "=f"(r) : "f"(a), "f"(b));
    return r;
}

// 9-slot histogram bucket address; slot = |fa - (signs_differ ? 8 : 0)| = fl mod 9
__device__ __forceinline__ uint32_t hog_class(float gx, float gy, uint32_t hb, float& mag)
{
    float d2 = fmaf(gx, gx, gy * gy);
    asm("sqrt.approx.f32 %0, %1;" : "=f"(mag) : "f"(d2));

    float u = fabsf(gx), v = fabsf(gy);
    float fa = (setge(u, 0.36397023f * v) + setge(u, 0.83909963f * v))
             + (setge(u, 1.73205081f * v) + setge(u, 5.67128182f * v));  // 0..4

    uint32_t xo = __float_as_uint(gx) ^ __float_as_uint(gy);
    float cf8 = ((int)xo < 0) ? 8.0f : 0.0f;
    float m = fabsf(fa - cf8) + 12582912.0f;     // 0x4B400000 + slot (exact)
    return hb + (__float_as_uint(m) << 10);
}

__device__ __forceinline__ void hog_pair(uint32_t a0, float m0, uint32_t a1, float m1)
{
    float msum = m0 + m1;
    asm volatile(
        "{\n\t"
        ".reg .pred p;\n\t"
        ".reg .f32 t0, t1, v0;\n\t"
        "setp.ne.u32 p, %0, %1;\n\t"
        "selp.f32 v0, %2, %3, p;\n\t"
        "ld.shared.f32 t0, [%0];\n\t"
        "@p ld.shared.f32 t1, [%1];\n\t"
        "add.f32 t0, t0, v0;\n\t"
        "@p add.f32 t1, t1, %4;\n\t"
        "st.shared.f32 [%0], t0;\n\t"
        "@p st.shared.f32 [%1], t1;\n\t"
        "}"
        :: "r"(a0), "r"(a1), "f"(m0), "f"(msum), "f"(m1));
}

__device__ __forceinline__ void emit(uint32_t hb, float gx0, float gy0, float gx1, float gy1)
{
    float m0, m1;
    uint32_t q0 = hog_class(gx0, gy0, hb, m0);
    uint32_t q1 = hog_class(gx1, gy1, hb, m1);
    hog_pair(q0, m0, q1, m1);
}

__global__ __launch_bounds__(256, 6)
void hog_kernel(const float* __restrict__ x, float* __restrict__ out)
{
    __shared__ __align__(16) float tile[10 * TS2];
    __shared__ float hist[9 * 256];

    const int tid = threadIdx.x;
    const int n   = blockIdx.x >> 6;
    const int cy  = blockIdx.x & 63;

#pragma unroll
    for (int b = 0; b < 9; ++b) hist[b * 256 + tid] = 0.0f;

    // ---- tile fill: 10 rows x 256 8-byte chunks via cp.async ----
    // iteration i covers tile row i (stripe row i-1); OOB rows warp-uniform.
    const float* img  = x + (size_t)n * (512 * 512);
    const int    row0 = cy * 8 - 1;
    const uint32_t tb = smem_u32(tile);
    const int p   = tid;                               // 8B-pair index: cols 2p,2p+1... (p<256)
    const uint32_t dcol = (uint32_t)(10 * (p >> 2) + 2 * (p & 3) + 4);
#pragma unroll
    for (int i = 0; i < 10; ++i) {
        int gr = row0 + i;
        const float* src = img + (size_t)((unsigned)gr < 512u ? gr : 0) * 512 + 2 * p;
        uint32_t dst = tb + (i * TS2 + dcol) * 4;
        if ((unsigned)gr < 512u) cp_async8(dst, src);
        else                     cp_async8_zero(dst, src);
    }
    if (tid < 10) { tile[tid * TS2 + 1] = 0.f; tile[tid * TS2 + 644] = 0.f; }  // edge pads
    asm volatile("cp.async.commit_group;" ::: "memory");
    asm volatile("cp.async.wait_group 0;" ::: "memory");
    __syncthreads();

    // ---- mainloop: thread = cell (8 cols) x 2 rows; 2 cols per step ----
    const int cell = tid >> 2;
    const int sub  = tid & 3;
    const float* pw = &tile[(2 * sub + 0) * TS2 + 10 * cell];
    const float* pa = &tile[(2 * sub + 1) * TS2 + 10 * cell];
    const float* pb = &tile[(2 * sub + 2) * TS2 + 10 * cell];
    const float* pc = &tile[(2 * sub + 3) * TS2 + 10 * cell];
    const uint32_t hb = smem_u32(&hist[tid]);

    float lw = pw[1], la = pa[1], lb = pb[1], lc = pc[1];   // col 8c-1
    float2 wp = *reinterpret_cast<const float2*>(pw + 4);
    float2 ap = *reinterpret_cast<const float2*>(pa + 4);
    float2 bp = *reinterpret_cast<const float2*>(pb + 4);
    float2 cp = *reinterpret_cast<const float2*>(pc + 4);

    float Am1 = lw + 2.f * la + lb;
    float Bm1 = la + 2.f * lb + lc;
    float A0 = wp.x + 2.f * ap.x + bp.x, A1 = wp.y + 2.f * ap.y + bp.y;
    float B0 = ap.x + 2.f * bp.x + cp.x, B1 = ap.y + 2.f * bp.y + cp.y;

    emit(hb,
         Am1 - A1, (lw + 2.f * wp.x + wp.y) - (lb + 2.f * bp.x + bp.y),
         Bm1 - B1, (la + 2.f * ap.x + ap.y) - (lc + 2.f * cp.x + cp.y));

    float w0 = wp.x, w1 = wp.y, a0 = ap.x, a1 = ap.y;
    float b0 = bp.x, b1 = bp.y, c0 = cp.x, c1 = cp.y;

#pragma unroll
    for (int k = 1; k < 4; ++k) {
        float2 wn = *reinterpret_cast<const float2*>(pw + 4 + 2 * k);
        float2 an = *reinterpret_cast<const float2*>(pa + 4 + 2 * k);
        float2 bn = *reinterpret_cast<const float2*>(pb + 4 + 2 * k);
        float2 cn = *reinterpret_cast<const float2*>(pc + 4 + 2 * k);
        float A2 = wn.x + 2.f * an.x + bn.x, A3 = wn.y + 2.f * an.y + bn.y;
        float B2 = an.x + 2.f * bn.x + cn.x, B3 = an.y + 2.f * bn.y + cn.y;

        emit(hb,
             A0 - A2, (w0 + 2.f * w1 + wn.x) - (b0 + 2.f * b1 + bn.x),
             B0 - B2, (a0 + 2.f * a1 + an.x) - (c0 + 2.f * c1 + cn.x));
        emit(hb,
             A1 - A3, (w1 + 2.f * wn.x + wn.y) - (b1 + 2.f * bn.x + bn.y),
             B1 - B3, (a1 + 2.f * an.x + an.y) - (c1 + 2.f * cn.x + cn.y));

        w0 = wn.x; w1 = wn.y; a0 = an.x; a1 = an.y;
        b0 = bn.x; b1 = bn.y; c0 = cn.x; c1 = cn.y;
        A0 = A2; A1 = A3; B0 = B2; B1 = B3;
    }

    // tail: col 7 with right halo col 8 (idx 10c+14)
    {
        float rw = pw[14], ra = pa[14], rb = pb[14], rc = pc[14];
        float A8 = rw + 2.f * ra + rb;
        float B8 = ra + 2.f * rb + rc;
        emit(hb,
             A0 - A8, (w0 + 2.f * w1 + rw) - (b0 + 2.f * b1 + rb),
             B0 - B8, (a0 + 2.f * a1 + ra) - (c0 + 2.f * c1 + rc));
    }

    asm volatile("" ::: "memory");   // order fold reads after asm RMWs

    // ---- fold: bin[b] = P9[b] + P9[(b+8)%9]; shuffle-reduce 4 subs; write ----
    float P[9];
#pragma unroll
    for (int s = 0; s < 9; ++s) P[s] = hist[s * 256 + tid];
    float bin[9];
#pragma unroll
    for (int b = 0; b < 9; ++b) bin[b] = P[b] + P[(b + 8) % 9];

#pragma unroll
    for (int b = 0; b < 9; ++b) {
        bin[b] += __shfl_xor_sync(0xffffffffu, bin[b], 1);
        bin[b] += __shfl_xor_sync(0xffffffffu, bin[b], 2);
    }

    if (sub == 0) {
        float* o = out + (size_t)n * 36864 + cy * 64 + cell;
#pragma unroll
        for (int b = 0; b < 9; ++b)
            o[(size_t)b * 4096] = bin[b] * 0.015625f;   // 1/64
    }
}

extern "C" void kernel_launch(void* const* d_in, const int* in_sizes, int n_in,
                              void* d_out, int out_size)
{
    const float* x = (const float*)d_in[0];
    float* out = (float*)d_out;
    (void)in_sizes; (void)n_in; (void)out_size;
    hog_kernel<<<4096, 256>>>(x, out);
}